// round 16
// baseline (speedup 1.0000x reference)
#include <cuda_runtime.h>
#include <cuda_fp16.h>
#include <cstdint>

#define BT   4096
#define DIM  1024
#define NEXP 8
#define HID  2048

#define XSZ  ((size_t)BT * DIM)
#define HSZ  ((size_t)BT * HID)
#define WSZ  ((size_t)NEXP * HID * DIM)

// ---------------------------------------------------------------------------
__device__ int g_cnt[NEXP];
__device__ int g_list[NEXP][BT];
__device__ __align__(16) __half g_x[XSZ];
__device__ __align__(16) __half g_h[HSZ];
__device__ __align__(16) __half g_Wg[WSZ];
__device__ __align__(16) __half g_Wu[WSZ];
__device__ __align__(16) __half g_Wd[WSZ];

// ---------------------------------------------------------------------------
__device__ __forceinline__ uint32_t smem_to_u32(const void* smem_ptr) {
    uint32_t addr;
    asm("{ .reg .u64 tmp; cvta.to.shared.u64 tmp, %1; cvt.u32.u64 %0, tmp; }"
        : "=r"(addr) : "l"(smem_ptr));
    return addr;
}

__device__ __forceinline__ void cp16(uint32_t dst, const void* src, uint32_t sz) {
    asm volatile("cp.async.cg.shared.global [%0], [%1], 16, %2;\n"
                 :: "r"(dst), "l"(src), "r"(sz));
}
#define CP_COMMIT() asm volatile("cp.async.commit_group;\n" ::: "memory")
#define CP_WAIT1()  asm volatile("cp.async.wait_group 1;\n" ::: "memory")

__device__ __forceinline__ void ldsm_x4(uint32_t* r, uint32_t addr) {
    asm volatile("ldmatrix.sync.aligned.m8n8.x4.shared.b16 {%0,%1,%2,%3}, [%4];"
        : "=r"(r[0]), "=r"(r[1]), "=r"(r[2]), "=r"(r[3]) : "r"(addr));
}
__device__ __forceinline__ void ldsm_x4t(uint32_t* r, uint32_t addr) {
    asm volatile("ldmatrix.sync.aligned.m8n8.x4.trans.shared.b16 {%0,%1,%2,%3}, [%4];"
        : "=r"(r[0]), "=r"(r[1]), "=r"(r[2]), "=r"(r[3]) : "r"(addr));
}

#define MMA_F16(acc, a, b0, b1) \
    asm volatile("mma.sync.aligned.m16n8k16.row.col.f32.f16.f16.f32 " \
        "{%0,%1,%2,%3}, {%4,%5,%6,%7}, {%8,%9}, {%0,%1,%2,%3};" \
        : "+f"((acc)[0]), "+f"((acc)[1]), "+f"((acc)[2]), "+f"((acc)[3]) \
        : "r"((a)[0]), "r"((a)[1]), "r"((a)[2]), "r"((a)[3]), \
          "r"(b0), "r"(b1))

// convert 8 consecutive floats -> 8 halves.
// Source: __ldcs (fp32 never re-read -> evict-first).
// Dest: PLAIN store (fp16 weights re-read by the GEMM soon -> keep in L2).
__device__ __forceinline__ void cvt8(const float* __restrict__ s,
                                     __half* __restrict__ d) {
    float4 v0 = __ldcs((const float4*)s);
    float4 v1 = __ldcs((const float4*)(s + 4));
    __half h[8];
    h[0] = __float2half_rn(v0.x); h[1] = __float2half_rn(v0.y);
    h[2] = __float2half_rn(v0.z); h[3] = __float2half_rn(v0.w);
    h[4] = __float2half_rn(v1.x); h[5] = __float2half_rn(v1.y);
    h[6] = __float2half_rn(v1.z); h[7] = __float2half_rn(v1.w);
    *(uint4*)d = *(uint4*)h;
}

// ---------------------------------------------------------------------------
__global__ void init_kernel() {
    if (threadIdx.x < NEXP) g_cnt[threadIdx.x] = 0;
}

// ---------------------------------------------------------------------------
// Fused: x convert (fp16) + gating + scatter + Wg/Wu fp32->fp16 conversion.
// One token/block; each block also converts a 4096-float slice of Wg and Wu.
// ---------------------------------------------------------------------------
__global__ __launch_bounds__(256) void gate_convert_kernel(
        const float* __restrict__ x, const float* __restrict__ gw,
        const float* __restrict__ wg_src, const float* __restrict__ wu_src) {
    __shared__ float red[8][8];
    __shared__ float logits[8];
    const int t = blockIdx.x;
    const int tid = threadIdx.x;
    const int lane = tid & 31, wid = tid >> 5;

    float4 v = ((const float4*)x)[(size_t)t * (DIM / 4) + tid];

    __half2 p0 = __halves2half2(__float2half_rn(v.x), __float2half_rn(v.y));
    __half2 p1 = __halves2half2(__float2half_rn(v.z), __float2half_rn(v.w));
    size_t o = (size_t)t * DIM + tid * 4;
    *(__half2*)(g_x + o)     = p0;
    *(__half2*)(g_x + o + 2) = p1;

    float acc[NEXP];
#pragma unroll
    for (int e = 0; e < NEXP; e++) {
        float4 g = ((const float4*)(gw + (size_t)e * DIM))[tid];
        acc[e] = v.x * g.x + v.y * g.y + v.z * g.z + v.w * g.w;
    }
#pragma unroll
    for (int e = 0; e < NEXP; e++) {
#pragma unroll
        for (int off = 16; off > 0; off >>= 1)
            acc[e] += __shfl_xor_sync(0xffffffffu, acc[e], off);
    }
    if (lane == 0) {
#pragma unroll
        for (int e = 0; e < NEXP; e++) red[wid][e] = acc[e];
    }
    __syncthreads();
    if (tid < 8) {
        float s = 0.f;
#pragma unroll
        for (int w = 0; w < 8; w++) s += red[w][tid];
        logits[tid] = s;
    }
    __syncthreads();
    if (tid == 0) {
        int best = 0; float bv = logits[0];
#pragma unroll
        for (int e = 1; e < NEXP; e++)
            if (logits[e] > bv) { bv = logits[e]; best = e; }
        int p = atomicAdd(&g_cnt[best], 1);
        g_list[best][p] = t;
    }

    // Convert Wg/Wu slices: 4096 floats per matrix per block = 16/thread.
    {
        size_t base = (size_t)t * 4096 + (size_t)tid * 16;
        cvt8(wg_src + base,     g_Wg + base);
        cvt8(wg_src + base + 8, g_Wg + base + 8);
        cvt8(wu_src + base,     g_Wu + base);
        cvt8(wu_src + base + 8, g_Wu + base + 8);
    }
}

// ---------------------------------------------------------------------------
// smem geometry (halves). K-chunk = 64, 3 stages.
// ---------------------------------------------------------------------------
#define KC     64
#define LDA    72
#define LDB    72
#define LDB2   136
#define OFF_B  9216
#define BMAT   (64 * LDB)              // 4608 halves
#define STG1   (OFF_B + 2 * BMAT)      // 18432
#define STG2   (OFF_B + 64 * LDB2)     // 17920
#define SMEM1  (3 * STG1 * 2 + 512)
#define SMEM2  (3 * STG2 * 2 + 512)

// ---------------------------------------------------------------------------
// FFN1: a = xWg, u = xWu, h = silu(a)*u -> fp16
// CTA 128 tok x 64 cols, 8 warps 32x32 (wm 4 x wn 2), K-chunk 64.
// Fragment pipeline (A/Bg double-buffered, Bu hidden behind gate burst).
// Prologue converts a 2048-float slice of Wd (overlapped; for ffn2).
// ---------------------------------------------------------------------------
__global__ __launch_bounds__(256, 2) void ffn1_kernel(
        const float* __restrict__ wd_src) {
    extern __shared__ __align__(16) __half sm[];
    const int tid = threadIdx.x;

    {
        size_t cta = (size_t)blockIdx.x +
                     (size_t)gridDim.x * (blockIdx.y + (size_t)gridDim.y * blockIdx.z);
        size_t base = cta * 2048 + (size_t)tid * 8;
        cvt8(wd_src + base, g_Wd + base);
    }

    const int e = blockIdx.z;
    const int cnt = g_cnt[e];
    const int row0 = blockIdx.x * 128;
    if (row0 >= cnt) return;
    const int col0 = blockIdx.y * 64;
    const int lane = tid & 31, wid = tid >> 5;
    const int wm = (wid & 3) * 32, wn = (wid >> 2) * 32;

    int* toks = (int*)(sm + 3 * STG1);
    if (tid < 128) {
        int r = row0 + tid;
        toks[tid] = (r < cnt) ? g_list[e][r] : -1;
    }
    __syncthreads();
    const uint32_t sbase = smem_to_u32(sm);
    const size_t wbase = (size_t)e * DIM * HID + col0;

    auto issue = [&](int ko, uint32_t sb) {
#pragma unroll
        for (int j = 0; j < 4; j++) {
            int idx = tid + j * 256;
            int r = idx >> 3, s = idx & 7;
            int t = toks[r];
            const __half* ap = g_x + (size_t)(t < 0 ? 0 : t) * DIM + ko + s * 8;
            cp16(sb + (uint32_t)(r * LDA + s * 8) * 2, ap, t >= 0 ? 16u : 0u);
        }
#pragma unroll
        for (int j = 0; j < 2; j++) {
            int idx = tid + j * 256;
            int rb = idx >> 3, sbk = idx & 7;
            size_t w = wbase + (size_t)(ko + rb) * HID + sbk * 8;
            uint32_t d = sb + (uint32_t)(OFF_B + rb * LDB + sbk * 8) * 2;
            cp16(d,            g_Wg + w, 16);
            cp16(d + BMAT * 2, g_Wu + w, 16);
        }
    };

    float accg[2][4][4], accu[2][4][4];
#pragma unroll
    for (int mt = 0; mt < 2; mt++)
#pragma unroll
        for (int nt = 0; nt < 4; nt++)
#pragma unroll
            for (int j = 0; j < 4; j++) { accg[mt][nt][j] = 0.f; accu[mt][nt][j] = 0.f; }

    const int lq = lane & 15, lh = lane >> 4;
    const uint32_t aAddr = sbase + (uint32_t)((wm + lq) * LDA + 8 * lh) * 2;
    const uint32_t bAddr = sbase + (uint32_t)(OFF_B + lq * LDB + wn + 8 * lh) * 2;

    uint32_t aF[2][2][4], bgF[2][2][4], buF[2][4];

    auto ldA = [&](int set, uint32_t stg, int ks) {
#pragma unroll
        for (int mt = 0; mt < 2; mt++)
            ldsm_x4(aF[set][mt], aAddr + stg + (uint32_t)(mt * 16 * LDA + ks) * 2);
    };
    auto ldBg = [&](int set, uint32_t stg, int ks) {
#pragma unroll
        for (int n2 = 0; n2 < 2; n2++)
            ldsm_x4t(bgF[set][n2], bAddr + stg + (uint32_t)(ks * LDB + n2 * 16) * 2);
    };
    auto ldBu = [&](uint32_t stg, int ks) {
#pragma unroll
        for (int n2 = 0; n2 < 2; n2++)
            ldsm_x4t(buF[n2], bAddr + stg + (uint32_t)(ks * LDB + n2 * 16) * 2 + BMAT * 2);
    };
    auto mmas = [&](int set) {
#pragma unroll
        for (int mt = 0; mt < 2; mt++)
#pragma unroll
            for (int nt = 0; nt < 4; nt++) {
                uint32_t* pg = &bgF[set][nt >> 1][(nt & 1) * 2];
                MMA_F16(accg[mt][nt], aF[set][mt], pg[0], pg[1]);
            }
#pragma unroll
        for (int mt = 0; mt < 2; mt++)
#pragma unroll
            for (int nt = 0; nt < 4; nt++) {
                uint32_t* pu = &buF[nt >> 1][(nt & 1) * 2];
                MMA_F16(accu[mt][nt], aF[set][mt], pu[0], pu[1]);
            }
    };

    const int NK = DIM / KC;   // 16

    issue(0, sbase);            CP_COMMIT();
    issue(KC, sbase + STG1 * 2); CP_COMMIT();
    CP_WAIT1();

    int stage = 0;
    for (int i = 0; i < NK; i++) {
        __syncthreads();

        ldA(0, (uint32_t)(stage * STG1 * 2), 0);
        ldBg(0, (uint32_t)(stage * STG1 * 2), 0);

        if (i + 2 < NK) {
            int ps = stage + 2; if (ps >= 3) ps -= 3;
            issue((i + 2) * KC, sbase + (uint32_t)(ps * STG1 * 2));
        }
        CP_COMMIT();

        uint32_t stg = (uint32_t)(stage * STG1 * 2);
#pragma unroll
        for (int g = 0; g < 4; g++) {
            const int cur = g & 1;
            ldBu(stg, g * 16);
            if (g < 3) {
                ldA(cur ^ 1, stg, (g + 1) * 16);
                ldBg(cur ^ 1, stg, (g + 1) * 16);
            }
            mmas(cur);
        }
        CP_WAIT1();
        stage++; if (stage >= 3) stage = 0;
    }

    const int lr = lane >> 2, lk = (lane & 3) * 2;
#pragma unroll
    for (int mt = 0; mt < 2; mt++) {
        int ra = wm + mt * 16 + lr;
        int ta = toks[ra], tb = toks[ra + 8];
#pragma unroll
        for (int nt = 0; nt < 4; nt++) {
            int col = col0 + wn + nt * 8 + lk;
            if (ta >= 0) {
                float a0v = accg[mt][nt][0], a1v = accg[mt][nt][1];
                float u0v = accu[mt][nt][0], u1v = accu[mt][nt][1];
                float hv0 = a0v * u0v / (1.f + __expf(-a0v));
                float hv1 = a1v * u1v / (1.f + __expf(-a1v));
                *(__half2*)(g_h + (size_t)ta * HID + col) =
                    __halves2half2(__float2half_rn(hv0), __float2half_rn(hv1));
            }
            if (tb >= 0) {
                float a0v = accg[mt][nt][2], a1v = accg[mt][nt][3];
                float u0v = accu[mt][nt][2], u1v = accu[mt][nt][3];
                float hv0 = a0v * u0v / (1.f + __expf(-a0v));
                float hv1 = a1v * u1v / (1.f + __expf(-a1v));
                *(__half2*)(g_h + (size_t)tb * HID + col) =
                    __halves2half2(__float2half_rn(hv0), __float2half_rn(hv1));
            }
        }
    }
}

// ---------------------------------------------------------------------------
// FFN2: out = h Wd (fp32). CTA 128 x 128, 8 warps 32x64 (wm 4 x wn 2),
// K-chunk 64, full A+B fragment double-buffering.
// ---------------------------------------------------------------------------
__global__ __launch_bounds__(256, 2) void ffn2_kernel(float* __restrict__ out) {
    extern __shared__ __align__(16) __half sm[];
    const int e = blockIdx.z;
    const int cnt = g_cnt[e];
    const int row0 = blockIdx.x * 128;
    if (row0 >= cnt) return;
    const int col0 = blockIdx.y * 128;
    const int tid = threadIdx.x, lane = tid & 31, wid = tid >> 5;
    const int wm = (wid & 3) * 32, wn = (wid >> 2) * 64;

    int* toks = (int*)(sm + 3 * STG2);
    if (tid < 128) {
        int r = row0 + tid;
        toks[tid] = (r < cnt) ? g_list[e][r] : -1;
    }
    __syncthreads();
    const uint32_t sbase = smem_to_u32(sm);
    const size_t wbase = (size_t)e * HID * DIM + col0;

    auto issue = [&](int ko, uint32_t sb) {
#pragma unroll
        for (int j = 0; j < 4; j++) {
            int idx = tid + j * 256;
            int r = idx >> 3, s = idx & 7;
            int t = toks[r];
            const __half* ap = g_h + (size_t)(t < 0 ? 0 : t) * HID + ko + s * 8;
            cp16(sb + (uint32_t)(r * LDA + s * 8) * 2, ap, t >= 0 ? 16u : 0u);
        }
#pragma unroll
        for (int j = 0; j < 4; j++) {
            int idx = tid + j * 256;
            int rb = idx >> 4, sbk = idx & 15;
            size_t w = wbase + (size_t)(ko + rb) * DIM + sbk * 8;
            cp16(sb + (uint32_t)(OFF_B + rb * LDB2 + sbk * 8) * 2, g_Wd + w, 16);
        }
    };

    float acc[2][8][4];
#pragma unroll
    for (int mt = 0; mt < 2; mt++)
#pragma unroll
        for (int nt = 0; nt < 8; nt++)
#pragma unroll
            for (int j = 0; j < 4; j++) acc[mt][nt][j] = 0.f;

    const int lq = lane & 15, lh = lane >> 4;
    const uint32_t aAddr = sbase + (uint32_t)((wm + lq) * LDA + 8 * lh) * 2;
    const uint32_t bAddr = sbase + (uint32_t)(OFF_B + lq * LDB2 + wn + 8 * lh) * 2;

    uint32_t aF[2][2][4], bF[2][4][4];

    auto ldA = [&](int set, uint32_t stg, int ks) {
#pragma unroll
        for (int mt = 0; mt < 2; mt++)
            ldsm_x4(aF[set][mt], aAddr + stg + (uint32_t)(mt * 16 * LDA + ks) * 2);
    };
    auto ldB = [&](int set, uint32_t stg, int ks) {
#pragma unroll
        for (int n2 = 0; n2 < 4; n2++)
            ldsm_x4t(bF[set][n2], bAddr + stg + (uint32_t)(ks * LDB2 + n2 * 16) * 2);
    };
    auto mmas = [&](int set) {
#pragma unroll
        for (int mt = 0; mt < 2; mt++)
#pragma unroll
            for (int nt = 0; nt < 8; nt++) {
                uint32_t* pb = &bF[set][nt >> 1][(nt & 1) * 2];
                MMA_F16(acc[mt][nt], aF[set][mt], pb[0], pb[1]);
            }
    };

    const int NK = HID / KC;   // 32

    issue(0, sbase);            CP_COMMIT();
    issue(KC, sbase + STG2 * 2); CP_COMMIT();
    CP_WAIT1();

    int stage = 0;
    for (int i = 0; i < NK; i++) {
        __syncthreads();

        ldA(0, (uint32_t)(stage * STG2 * 2), 0);
        ldB(0, (uint32_t)(stage * STG2 * 2), 0);

        if (i + 2 < NK) {
            int ps = stage + 2; if (ps >= 3) ps -= 3;
            issue((i + 2) * KC, sbase + (uint32_t)(ps * STG2 * 2));
        }
        CP_COMMIT();

        uint32_t stg = (uint32_t)(stage * STG2 * 2);
#pragma unroll
        for (int g = 0; g < 4; g++) {
            const int cur = g & 1;
            if (g < 3) {
                ldA(cur ^ 1, stg, (g + 1) * 16);
                ldB(cur ^ 1, stg, (g + 1) * 16);
            }
            mmas(cur);
        }
        CP_WAIT1();
        stage++; if (stage >= 3) stage = 0;
    }

    const int lr = lane >> 2, lk = (lane & 3) * 2;
#pragma unroll
    for (int mt = 0; mt < 2; mt++) {
        int ra = wm + mt * 16 + lr;
        int ta = toks[ra], tb = toks[ra + 8];
#pragma unroll
        for (int nt = 0; nt < 8; nt++) {
            int col = col0 + wn + nt * 8 + lk;
            if (ta >= 0)
                *(float2*)(out + (size_t)ta * DIM + col) =
                    make_float2(acc[mt][nt][0], acc[mt][nt][1]);
            if (tb >= 0)
                *(float2*)(out + (size_t)tb * DIM + col) =
                    make_float2(acc[mt][nt][2], acc[mt][nt][3]);
        }
    }
}

// ---------------------------------------------------------------------------
extern "C" void kernel_launch(void* const* d_in, const int* in_sizes, int n_in,
                              void* d_out, int out_size) {
    const float* x         = (const float*)d_in[0];
    const float* gate_w    = (const float*)d_in[1];
    const float* gate_bank = (const float*)d_in[2];
    const float* up_bank   = (const float*)d_in[3];
    const float* down_bank = (const float*)d_in[4];
    float* out = (float*)d_out;

    cudaFuncSetAttribute(ffn1_kernel,
                         cudaFuncAttributeMaxDynamicSharedMemorySize, SMEM1);
    cudaFuncSetAttribute(ffn2_kernel,
                         cudaFuncAttributeMaxDynamicSharedMemorySize, SMEM2);

    init_kernel<<<1, 32>>>();
    gate_convert_kernel<<<BT, 256>>>(x, gate_w, gate_bank, up_bank);
    ffn1_kernel<<<dim3(BT / 128, HID / 64, NEXP), 256, SMEM1>>>(down_bank);
    ffn2_kernel<<<dim3(BT / 128, DIM / 128, NEXP), 256, SMEM2>>>(out);
}

// round 17
// speedup vs baseline: 1.2863x; 1.2863x over previous
#include <cuda_runtime.h>
#include <cuda_fp16.h>
#include <cstdint>

#define BT   4096
#define DIM  1024
#define NEXP 8
#define HID  2048

#define XSZ  ((size_t)BT * DIM)
#define HSZ  ((size_t)BT * HID)
#define WSZ  ((size_t)NEXP * HID * DIM)

// ---------------------------------------------------------------------------
__device__ int g_cnt[NEXP];
__device__ int g_list[NEXP][BT];
__device__ __align__(16) __half g_x[XSZ];
__device__ __align__(16) __half g_h[HSZ];
__device__ __align__(16) __half g_Wg[WSZ];
__device__ __align__(16) __half g_Wu[WSZ];
__device__ __align__(16) __half g_Wd[WSZ];

// ---------------------------------------------------------------------------
__device__ __forceinline__ uint32_t smem_to_u32(const void* smem_ptr) {
    uint32_t addr;
    asm("{ .reg .u64 tmp; cvta.to.shared.u64 tmp, %1; cvt.u32.u64 %0, tmp; }"
        : "=r"(addr) : "l"(smem_ptr));
    return addr;
}

__device__ __forceinline__ void cp16(uint32_t dst, const void* src, uint32_t sz) {
    asm volatile("cp.async.cg.shared.global [%0], [%1], 16, %2;\n"
                 :: "r"(dst), "l"(src), "r"(sz));
}
#define CP_COMMIT() asm volatile("cp.async.commit_group;\n" ::: "memory")
#define CP_WAIT1()  asm volatile("cp.async.wait_group 1;\n" ::: "memory")

__device__ __forceinline__ void ldsm_x4(uint32_t* r, uint32_t addr) {
    asm volatile("ldmatrix.sync.aligned.m8n8.x4.shared.b16 {%0,%1,%2,%3}, [%4];"
        : "=r"(r[0]), "=r"(r[1]), "=r"(r[2]), "=r"(r[3]) : "r"(addr));
}
__device__ __forceinline__ void ldsm_x4t(uint32_t* r, uint32_t addr) {
    asm volatile("ldmatrix.sync.aligned.m8n8.x4.trans.shared.b16 {%0,%1,%2,%3}, [%4];"
        : "=r"(r[0]), "=r"(r[1]), "=r"(r[2]), "=r"(r[3]) : "r"(addr));
}

#define MMA_F16(acc, a, b0, b1) \
    asm volatile("mma.sync.aligned.m16n8k16.row.col.f32.f16.f16.f32 " \
        "{%0,%1,%2,%3}, {%4,%5,%6,%7}, {%8,%9}, {%0,%1,%2,%3};" \
        : "+f"((acc)[0]), "+f"((acc)[1]), "+f"((acc)[2]), "+f"((acc)[3]) \
        : "r"((a)[0]), "r"((a)[1]), "r"((a)[2]), "r"((a)[3]), \
          "r"(b0), "r"(b1))

// convert 8 consecutive floats -> 8 halves (one uint4 store)
__device__ __forceinline__ void cvt8(const float* __restrict__ s,
                                     __half* __restrict__ d) {
    float4 v0 = *(const float4*)s;
    float4 v1 = *(const float4*)(s + 4);
    __half h[8];
    h[0] = __float2half_rn(v0.x); h[1] = __float2half_rn(v0.y);
    h[2] = __float2half_rn(v0.z); h[3] = __float2half_rn(v0.w);
    h[4] = __float2half_rn(v1.x); h[5] = __float2half_rn(v1.y);
    h[6] = __float2half_rn(v1.z); h[7] = __float2half_rn(v1.w);
    *(uint4*)d = *(uint4*)h;
}

// ---------------------------------------------------------------------------
__global__ void init_kernel() {
    if (threadIdx.x < NEXP) g_cnt[threadIdx.x] = 0;
}

// ---------------------------------------------------------------------------
// Fused: x convert (fp16) + gating + scatter + Wg/Wu fp32->fp16 conversion.
// One token/block; each block also converts a 4096-float slice of Wg and Wu.
// ---------------------------------------------------------------------------
__global__ __launch_bounds__(256) void gate_convert_kernel(
        const float* __restrict__ x, const float* __restrict__ gw,
        const float* __restrict__ wg_src, const float* __restrict__ wu_src) {
    __shared__ float red[8][8];
    __shared__ float logits[8];
    const int t = blockIdx.x;
    const int tid = threadIdx.x;
    const int lane = tid & 31, wid = tid >> 5;

    float4 v = ((const float4*)x)[(size_t)t * (DIM / 4) + tid];

    __half2 p0 = __halves2half2(__float2half_rn(v.x), __float2half_rn(v.y));
    __half2 p1 = __halves2half2(__float2half_rn(v.z), __float2half_rn(v.w));
    size_t o = (size_t)t * DIM + tid * 4;
    *(__half2*)(g_x + o)     = p0;
    *(__half2*)(g_x + o + 2) = p1;

    float acc[NEXP];
#pragma unroll
    for (int e = 0; e < NEXP; e++) {
        float4 g = ((const float4*)(gw + (size_t)e * DIM))[tid];
        acc[e] = v.x * g.x + v.y * g.y + v.z * g.z + v.w * g.w;
    }
#pragma unroll
    for (int e = 0; e < NEXP; e++) {
#pragma unroll
        for (int off = 16; off > 0; off >>= 1)
            acc[e] += __shfl_xor_sync(0xffffffffu, acc[e], off);
    }
    if (lane == 0) {
#pragma unroll
        for (int e = 0; e < NEXP; e++) red[wid][e] = acc[e];
    }
    __syncthreads();
    if (tid < 8) {
        float s = 0.f;
#pragma unroll
        for (int w = 0; w < 8; w++) s += red[w][tid];
        logits[tid] = s;
    }
    __syncthreads();
    if (tid == 0) {
        int best = 0; float bv = logits[0];
#pragma unroll
        for (int e = 1; e < NEXP; e++)
            if (logits[e] > bv) { bv = logits[e]; best = e; }
        int p = atomicAdd(&g_cnt[best], 1);
        g_list[best][p] = t;
    }

    // Convert Wg/Wu slices: 4096 floats per matrix per block = 16/thread.
    {
        size_t base = (size_t)t * 4096 + (size_t)tid * 16;
        cvt8(wg_src + base,     g_Wg + base);
        cvt8(wg_src + base + 8, g_Wg + base + 8);
        cvt8(wu_src + base,     g_Wu + base);
        cvt8(wu_src + base + 8, g_Wu + base + 8);
    }
}

// ---------------------------------------------------------------------------
// smem geometry (halves). K-chunk = 64, 3 stages.
// ---------------------------------------------------------------------------
#define KC     64
#define LDA    72
#define LDB    72
#define LDB2   136
#define OFF_B  9216
#define BMAT   (64 * LDB)              // 4608 halves
#define STG1   (OFF_B + 2 * BMAT)      // 18432
#define STG2   (OFF_B + 64 * LDB2)     // 17920
#define SMEM1  (3 * STG1 * 2 + 512)
#define SMEM2  (3 * STG2 * 2 + 512)

// ---------------------------------------------------------------------------
// FFN1: a = xWg, u = xWu, h = silu(a)*u -> fp16
// CTA 128 tok x 64 cols, 8 warps 32x32 (wm 4 x wn 2), K-chunk 64.
// Fragment pipeline (A/Bg double-buffered, Bu hidden behind gate burst).
// Prologue converts a 2048-float slice of Wd (overlapped; for ffn2).
// ---------------------------------------------------------------------------
__global__ __launch_bounds__(256, 2) void ffn1_kernel(
        const float* __restrict__ wd_src) {
    extern __shared__ __align__(16) __half sm[];
    const int tid = threadIdx.x;

    {
        size_t cta = (size_t)blockIdx.x +
                     (size_t)gridDim.x * (blockIdx.y + (size_t)gridDim.y * blockIdx.z);
        size_t base = cta * 2048 + (size_t)tid * 8;
        cvt8(wd_src + base, g_Wd + base);
    }

    const int e = blockIdx.z;
    const int cnt = g_cnt[e];
    const int row0 = blockIdx.x * 128;
    if (row0 >= cnt) return;
    const int col0 = blockIdx.y * 64;
    const int lane = tid & 31, wid = tid >> 5;
    const int wm = (wid & 3) * 32, wn = (wid >> 2) * 32;

    int* toks = (int*)(sm + 3 * STG1);
    if (tid < 128) {
        int r = row0 + tid;
        toks[tid] = (r < cnt) ? g_list[e][r] : -1;
    }
    __syncthreads();
    const uint32_t sbase = smem_to_u32(sm);
    const size_t wbase = (size_t)e * DIM * HID + col0;

    auto issue = [&](int ko, uint32_t sb) {
#pragma unroll
        for (int j = 0; j < 4; j++) {
            int idx = tid + j * 256;
            int r = idx >> 3, s = idx & 7;
            int t = toks[r];
            const __half* ap = g_x + (size_t)(t < 0 ? 0 : t) * DIM + ko + s * 8;
            cp16(sb + (uint32_t)(r * LDA + s * 8) * 2, ap, t >= 0 ? 16u : 0u);
        }
#pragma unroll
        for (int j = 0; j < 2; j++) {
            int idx = tid + j * 256;
            int rb = idx >> 3, sbk = idx & 7;
            size_t w = wbase + (size_t)(ko + rb) * HID + sbk * 8;
            uint32_t d = sb + (uint32_t)(OFF_B + rb * LDB + sbk * 8) * 2;
            cp16(d,            g_Wg + w, 16);
            cp16(d + BMAT * 2, g_Wu + w, 16);
        }
    };

    float accg[2][4][4], accu[2][4][4];
#pragma unroll
    for (int mt = 0; mt < 2; mt++)
#pragma unroll
        for (int nt = 0; nt < 4; nt++)
#pragma unroll
            for (int j = 0; j < 4; j++) { accg[mt][nt][j] = 0.f; accu[mt][nt][j] = 0.f; }

    const int lq = lane & 15, lh = lane >> 4;
    const uint32_t aAddr = sbase + (uint32_t)((wm + lq) * LDA + 8 * lh) * 2;
    const uint32_t bAddr = sbase + (uint32_t)(OFF_B + lq * LDB + wn + 8 * lh) * 2;

    uint32_t aF[2][2][4], bgF[2][2][4], buF[2][4];

    auto ldA = [&](int set, uint32_t stg, int ks) {
#pragma unroll
        for (int mt = 0; mt < 2; mt++)
            ldsm_x4(aF[set][mt], aAddr + stg + (uint32_t)(mt * 16 * LDA + ks) * 2);
    };
    auto ldBg = [&](int set, uint32_t stg, int ks) {
#pragma unroll
        for (int n2 = 0; n2 < 2; n2++)
            ldsm_x4t(bgF[set][n2], bAddr + stg + (uint32_t)(ks * LDB + n2 * 16) * 2);
    };
    auto ldBu = [&](uint32_t stg, int ks) {
#pragma unroll
        for (int n2 = 0; n2 < 2; n2++)
            ldsm_x4t(buF[n2], bAddr + stg + (uint32_t)(ks * LDB + n2 * 16) * 2 + BMAT * 2);
    };
    auto mmas = [&](int set) {
#pragma unroll
        for (int mt = 0; mt < 2; mt++)
#pragma unroll
            for (int nt = 0; nt < 4; nt++) {
                uint32_t* pg = &bgF[set][nt >> 1][(nt & 1) * 2];
                MMA_F16(accg[mt][nt], aF[set][mt], pg[0], pg[1]);
            }
#pragma unroll
        for (int mt = 0; mt < 2; mt++)
#pragma unroll
            for (int nt = 0; nt < 4; nt++) {
                uint32_t* pu = &buF[nt >> 1][(nt & 1) * 2];
                MMA_F16(accu[mt][nt], aF[set][mt], pu[0], pu[1]);
            }
    };

    const int NK = DIM / KC;   // 16

    issue(0, sbase);            CP_COMMIT();
    issue(KC, sbase + STG1 * 2); CP_COMMIT();
    CP_WAIT1();

    int stage = 0;
    for (int i = 0; i < NK; i++) {
        __syncthreads();

        ldA(0, (uint32_t)(stage * STG1 * 2), 0);
        ldBg(0, (uint32_t)(stage * STG1 * 2), 0);

        if (i + 2 < NK) {
            int ps = stage + 2; if (ps >= 3) ps -= 3;
            issue((i + 2) * KC, sbase + (uint32_t)(ps * STG1 * 2));
        }
        CP_COMMIT();

        uint32_t stg = (uint32_t)(stage * STG1 * 2);
#pragma unroll
        for (int g = 0; g < 4; g++) {
            const int cur = g & 1;
            ldBu(stg, g * 16);
            if (g < 3) {
                ldA(cur ^ 1, stg, (g + 1) * 16);
                ldBg(cur ^ 1, stg, (g + 1) * 16);
            }
            mmas(cur);
        }
        CP_WAIT1();
        stage++; if (stage >= 3) stage = 0;
    }

    const int lr = lane >> 2, lk = (lane & 3) * 2;
#pragma unroll
    for (int mt = 0; mt < 2; mt++) {
        int ra = wm + mt * 16 + lr;
        int ta = toks[ra], tb = toks[ra + 8];
#pragma unroll
        for (int nt = 0; nt < 4; nt++) {
            int col = col0 + wn + nt * 8 + lk;
            if (ta >= 0) {
                float a0v = accg[mt][nt][0], a1v = accg[mt][nt][1];
                float u0v = accu[mt][nt][0], u1v = accu[mt][nt][1];
                float hv0 = a0v * u0v / (1.f + __expf(-a0v));
                float hv1 = a1v * u1v / (1.f + __expf(-a1v));
                *(__half2*)(g_h + (size_t)ta * HID + col) =
                    __halves2half2(__float2half_rn(hv0), __float2half_rn(hv1));
            }
            if (tb >= 0) {
                float a0v = accg[mt][nt][2], a1v = accg[mt][nt][3];
                float u0v = accu[mt][nt][2], u1v = accu[mt][nt][3];
                float hv0 = a0v * u0v / (1.f + __expf(-a0v));
                float hv1 = a1v * u1v / (1.f + __expf(-a1v));
                *(__half2*)(g_h + (size_t)tb * HID + col) =
                    __halves2half2(__float2half_rn(hv0), __float2half_rn(hv1));
            }
        }
    }
}

// ---------------------------------------------------------------------------
// FFN2: out = h Wd (fp32). CTA 128 x 128, 8 warps 32x64 (wm 4 x wn 2),
// K-chunk 64, full A+B fragment double-buffering.
// ---------------------------------------------------------------------------
__global__ __launch_bounds__(256, 2) void ffn2_kernel(float* __restrict__ out) {
    extern __shared__ __align__(16) __half sm[];
    const int e = blockIdx.z;
    const int cnt = g_cnt[e];
    const int row0 = blockIdx.x * 128;
    if (row0 >= cnt) return;
    const int col0 = blockIdx.y * 128;
    const int tid = threadIdx.x, lane = tid & 31, wid = tid >> 5;
    const int wm = (wid & 3) * 32, wn = (wid >> 2) * 64;

    int* toks = (int*)(sm + 3 * STG2);
    if (tid < 128) {
        int r = row0 + tid;
        toks[tid] = (r < cnt) ? g_list[e][r] : -1;
    }
    __syncthreads();
    const uint32_t sbase = smem_to_u32(sm);
    const size_t wbase = (size_t)e * HID * DIM + col0;

    auto issue = [&](int ko, uint32_t sb) {
#pragma unroll
        for (int j = 0; j < 4; j++) {
            int idx = tid + j * 256;
            int r = idx >> 3, s = idx & 7;
            int t = toks[r];
            const __half* ap = g_h + (size_t)(t < 0 ? 0 : t) * HID + ko + s * 8;
            cp16(sb + (uint32_t)(r * LDA + s * 8) * 2, ap, t >= 0 ? 16u : 0u);
        }
#pragma unroll
        for (int j = 0; j < 4; j++) {
            int idx = tid + j * 256;
            int rb = idx >> 4, sbk = idx & 15;
            size_t w = wbase + (size_t)(ko + rb) * DIM + sbk * 8;
            cp16(sb + (uint32_t)(OFF_B + rb * LDB2 + sbk * 8) * 2, g_Wd + w, 16);
        }
    };

    float acc[2][8][4];
#pragma unroll
    for (int mt = 0; mt < 2; mt++)
#pragma unroll
        for (int nt = 0; nt < 8; nt++)
#pragma unroll
            for (int j = 0; j < 4; j++) acc[mt][nt][j] = 0.f;

    const int lq = lane & 15, lh = lane >> 4;
    const uint32_t aAddr = sbase + (uint32_t)((wm + lq) * LDA + 8 * lh) * 2;
    const uint32_t bAddr = sbase + (uint32_t)(OFF_B + lq * LDB2 + wn + 8 * lh) * 2;

    uint32_t aF[2][2][4], bF[2][4][4];

    auto ldA = [&](int set, uint32_t stg, int ks) {
#pragma unroll
        for (int mt = 0; mt < 2; mt++)
            ldsm_x4(aF[set][mt], aAddr + stg + (uint32_t)(mt * 16 * LDA + ks) * 2);
    };
    auto ldB = [&](int set, uint32_t stg, int ks) {
#pragma unroll
        for (int n2 = 0; n2 < 4; n2++)
            ldsm_x4t(bF[set][n2], bAddr + stg + (uint32_t)(ks * LDB2 + n2 * 16) * 2);
    };
    auto mmas = [&](int set) {
#pragma unroll
        for (int mt = 0; mt < 2; mt++)
#pragma unroll
            for (int nt = 0; nt < 8; nt++) {
                uint32_t* pb = &bF[set][nt >> 1][(nt & 1) * 2];
                MMA_F16(acc[mt][nt], aF[set][mt], pb[0], pb[1]);
            }
    };

    const int NK = HID / KC;   // 32

    issue(0, sbase);            CP_COMMIT();
    issue(KC, sbase + STG2 * 2); CP_COMMIT();
    CP_WAIT1();

    int stage = 0;
    for (int i = 0; i < NK; i++) {
        __syncthreads();

        ldA(0, (uint32_t)(stage * STG2 * 2), 0);
        ldB(0, (uint32_t)(stage * STG2 * 2), 0);

        if (i + 2 < NK) {
            int ps = stage + 2; if (ps >= 3) ps -= 3;
            issue((i + 2) * KC, sbase + (uint32_t)(ps * STG2 * 2));
        }
        CP_COMMIT();

        uint32_t stg = (uint32_t)(stage * STG2 * 2);
#pragma unroll
        for (int g = 0; g < 4; g++) {
            const int cur = g & 1;
            if (g < 3) {
                ldA(cur ^ 1, stg, (g + 1) * 16);
                ldB(cur ^ 1, stg, (g + 1) * 16);
            }
            mmas(cur);
        }
        CP_WAIT1();
        stage++; if (stage >= 3) stage = 0;
    }

    const int lr = lane >> 2, lk = (lane & 3) * 2;
#pragma unroll
    for (int mt = 0; mt < 2; mt++) {
        int ra = wm + mt * 16 + lr;
        int ta = toks[ra], tb = toks[ra + 8];
#pragma unroll
        for (int nt = 0; nt < 8; nt++) {
            int col = col0 + wn + nt * 8 + lk;
            if (ta >= 0)
                *(float2*)(out + (size_t)ta * DIM + col) =
                    make_float2(acc[mt][nt][0], acc[mt][nt][1]);
            if (tb >= 0)
                *(float2*)(out + (size_t)tb * DIM + col) =
                    make_float2(acc[mt][nt][2], acc[mt][nt][3]);
        }
    }
}

// ---------------------------------------------------------------------------
extern "C" void kernel_launch(void* const* d_in, const int* in_sizes, int n_in,
                              void* d_out, int out_size) {
    const float* x         = (const float*)d_in[0];
    const float* gate_w    = (const float*)d_in[1];
    const float* gate_bank = (const float*)d_in[2];
    const float* up_bank   = (const float*)d_in[3];
    const float* down_bank = (const float*)d_in[4];
    float* out = (float*)d_out;

    cudaFuncSetAttribute(ffn1_kernel,
                         cudaFuncAttributeMaxDynamicSharedMemorySize, SMEM1);
    cudaFuncSetAttribute(ffn2_kernel,
                         cudaFuncAttributeMaxDynamicSharedMemorySize, SMEM2);

    init_kernel<<<1, 32>>>();
    gate_convert_kernel<<<BT, 256>>>(x, gate_w, gate_bank, up_bank);
    ffn1_kernel<<<dim3(BT / 128, HID / 64, NEXP), 256, SMEM1>>>(down_bank);
    ffn2_kernel<<<dim3(BT / 128, DIM / 128, NEXP), 256, SMEM2>>>(out);
}